// round 3
// baseline (speedup 1.0000x reference)
#include <cuda_runtime.h>
#include <cuda_bf16.h>

#define IMG_W 416
#define IMG_H 416
#define NCH   3
#define QPT   52                 // quads handled per thread-slot (thread does q and q+52)
#define TPB   256
#define ROWS_THREADS (IMG_H * QPT)              // 21632 threads per sample
#define BLKX  ((ROWS_THREADS + TPB - 1) / TPB)  // 85 blocks per sample

__global__ void __launch_bounds__(TPB)
sample_kernel(const float* __restrict__ img,
              const float* __restrict__ bb,
              const float* __restrict__ angle,
              const int*   __restrict__ pos_ptr,
              float* __restrict__ out) {
    __shared__ float th[6];

    const int n = blockIdx.y;

    if (threadIdx.x == 0) {
        float patch_ori = 300.0f;
        if (pos_ptr) {
            int pi = pos_ptr[0];
            patch_ori = (pi > 0 && pi < 1000000) ? (float)pi : __int_as_float(pi);
        }
        float x1 = bb[n * 6 + 0];
        float y1 = bb[n * 6 + 1];
        float x2 = bb[n * 6 + 2];
        float y2 = bb[n * 6 + 3];

        float bwv = (x2 - x1) * (float)IMG_W;
        float bhv = (y2 - y1) * (float)IMG_H;
        float cx  = (x1 + x2) * 0.5f;
        float cy  = (y1 + y2) * 0.5f - (y2 - y1) * 0.1f;
        float tx  = (0.5f - cx) * 2.0f;
        float ty  = (0.5f - cy) * 2.0f;
        float target = 0.2f * sqrtf(bwv * bwv + bhv * bhv);
        float scale  = __fdiv_rn(target, patch_ori);

        float a = angle[n];
        float s = sinf(a);
        float c = cosf(a);

        th[0] = __fdiv_rn(c, scale);
        th[1] = __fdiv_rn(s, scale);
        th[2] = __fdiv_rn(tx * c + ty * s, scale);
        th[3] = __fdiv_rn(-s, scale);
        th[4] = __fdiv_rn(c, scale);
        th[5] = __fdiv_rn(-tx * s + ty * c, scale);
    }
    __syncthreads();

    const int tid = blockIdx.x * TPB + threadIdx.x;
    const int y   = tid / QPT;
    const int q   = tid - y * QPT;
    if (y >= IMG_H) return;

    const float t00 = th[0], t01 = th[1], t02 = th[2];
    const float t10 = th[3], t11 = th[4], t12 = th[5];

    // ys = (2y+1)/416 - 1 (exact division, matches reference)
    const float ysv = __fdiv_rn(2.0f * (float)y + 1.0f, (float)IMG_W) - 1.0f;

    // ix(x) = fmaf(t00, x, Cx);  iy(x) = fmaf(t10, x, Cy)
    // derived from ix = 208*gx + 207.5, 208*xs = x - 207.5
    const float Cx = fmaf(208.0f, fmaf(t01, ysv, t02), fmaf(-207.5f, t00, 207.5f));
    const float Cy = fmaf(208.0f, fmaf(t11, ysv, t12), fmaf(-207.5f, t10, 207.5f));

    const int cs = IMG_H * IMG_W;
    const float* base = img + n * NCH * cs;
    float* orow = out + (size_t)(n * NCH * IMG_H + y) * IMG_W;

#pragma unroll
    for (int h = 0; h < 2; h++) {
        const int xbase = (q + h * QPT) * 4;

        float ixa[4], iya[4];
        bool any = false;
#pragma unroll
        for (int p = 0; p < 4; p++) {
            float xf = (float)(xbase + p);
            float ix = fmaf(t00, xf, Cx);
            float iy = fmaf(t10, xf, Cy);
            ixa[p] = ix;
            iya[p] = iy;
            any = any || (ix > -1.0f && ix < (float)IMG_W &&
                          iy > -1.0f && iy < (float)IMG_H);
        }

        if (!any) {
            // Fast path (~99.7%): pure streaming zero writes, no reads.
            const float4 z = make_float4(0.f, 0.f, 0.f, 0.f);
            __stcs((float4*)(orow + xbase),          z);
            __stcs((float4*)(orow + xbase + cs),     z);
            __stcs((float4*)(orow + xbase + 2 * cs), z);
            continue;
        }

        float acc0[4], acc1[4], acc2[4];
#pragma unroll
        for (int p = 0; p < 4; p++) {
            float ix = ixa[p], iy = iya[p];
            float fx0 = floorf(ix), fy0 = floorf(iy);
            int   x0  = (int)fx0,   y0  = (int)fy0;
            float wx1 = ix - fx0,   wy1 = iy - fy0;
            float wx0 = 1.0f - wx1, wy0 = 1.0f - wy1;

            bool vx0 = (x0 >= 0)  && (x0 < IMG_W);
            bool vx1 = (x0 >= -1) && (x0 < IMG_W - 1);
            bool vy0 = (y0 >= 0)  && (y0 < IMG_H);
            bool vy1 = (y0 >= -1) && (y0 < IMG_H - 1);

            float w00 = (vx0 && vy0) ? wx0 * wy0 : 0.0f;
            float w10 = (vx1 && vy0) ? wx1 * wy0 : 0.0f;
            float w01 = (vx0 && vy1) ? wx0 * wy1 : 0.0f;
            float w11 = (vx1 && vy1) ? wx1 * wy1 : 0.0f;

            float a0 = 0.f, a1 = 0.f, a2 = 0.f;
            int i00 = y0 * IMG_W + x0;
            if (w00 != 0.0f) {
                a0 = fmaf(w00, __ldg(base + i00), a0);
                a1 = fmaf(w00, __ldg(base + cs + i00), a1);
                a2 = fmaf(w00, __ldg(base + 2 * cs + i00), a2);
            }
            if (w10 != 0.0f) {
                int i = i00 + 1;
                a0 = fmaf(w10, __ldg(base + i), a0);
                a1 = fmaf(w10, __ldg(base + cs + i), a1);
                a2 = fmaf(w10, __ldg(base + 2 * cs + i), a2);
            }
            if (w01 != 0.0f) {
                int i = i00 + IMG_W;
                a0 = fmaf(w01, __ldg(base + i), a0);
                a1 = fmaf(w01, __ldg(base + cs + i), a1);
                a2 = fmaf(w01, __ldg(base + 2 * cs + i), a2);
            }
            if (w11 != 0.0f) {
                int i = i00 + IMG_W + 1;
                a0 = fmaf(w11, __ldg(base + i), a0);
                a1 = fmaf(w11, __ldg(base + cs + i), a1);
                a2 = fmaf(w11, __ldg(base + 2 * cs + i), a2);
            }
            acc0[p] = a0;
            acc1[p] = a1;
            acc2[p] = a2;
        }

        __stcs((float4*)(orow + xbase),
               make_float4(acc0[0], acc0[1], acc0[2], acc0[3]));
        __stcs((float4*)(orow + xbase + cs),
               make_float4(acc1[0], acc1[1], acc1[2], acc1[3]));
        __stcs((float4*)(orow + xbase + 2 * cs),
               make_float4(acc2[0], acc2[1], acc2[2], acc2[3]));
    }
}

extern "C" void kernel_launch(void* const* d_in, const int* in_sizes, int n_in,
                              void* d_out, int out_size) {
    const float* img = (const float*)d_in[0];   // adv_patch_batch (B,L,C,H,W) f32
    const float* bb  = (const float*)d_in[1];   // bboxes_batch (B,L,6) f32
    const float* ang = (const float*)d_in[2];   // angle (B*L,) f32
    const int*   pos = (n_in > 3) ? (const int*)d_in[3] : nullptr;

    int N = in_sizes[2];                        // B*L = 128

    dim3 grid(BLKX, N);
    sample_kernel<<<grid, TPB>>>(img, bb, ang, pos, (float*)d_out);
}